// round 1
// baseline (speedup 1.0000x reference)
#include <cuda_runtime.h>
#include <math.h>

// ---------------- constants ----------------
#define RES   56
#define WS    7
#define SHIFT 3
#define DIM   192
#define HEADS 6
#define HD    32          // head dim
#define NTOK  49          // window tokens
#define BATCH 32
#define NWIN  64          // windows per image (8x8)
#define BW    (BATCH*NWIN)        // 2048 windows
#define TTOK  (BW*NTOK)           // 100352 rows (= B*L)
#define SCALE 0.17677669529663687f  // 32^-0.5

// ---------------- scratch (device globals; no allocation allowed) ----------------
__device__ float g_hln[TTOK*DIM];     // ln1 output (window order); reused for ln2 output
__device__ float g_q  [TTOK*DIM];     // [win][head][n][32]
__device__ float g_k  [TTOK*DIM];
__device__ float g_v  [TTOK*DIM];
__device__ float g_ao [TTOK*DIM];     // attention output, window-row order, [m][192]
__device__ float g_xn [TTOK*DIM];     // x after attention residual (token order)
__device__ float g_ml [TTOK*4*DIM];   // fc1+gelu output

// window-row m -> original token index (also the inverse scatter target)
__device__ __forceinline__ int win_src_token(int m) {
    int win = m / NTOK, n = m - win * NTOK;
    int b   = win >> 6, wi = win & 63;
    int wy  = wi >> 3,  wx = wi & 7;
    int py  = n / WS,   px = n - py * WS;
    int y = wy * WS + py + SHIFT; if (y >= RES) y -= RES;
    int x = wx * WS + px + SHIFT; if (x >= RES) x -= RES;
    return b * (RES*RES) + y * RES + x;
}

__device__ __forceinline__ int region(int c) {   // img slice label along one axis
    return (c < RES - WS) ? 0 : ((c < RES - SHIFT) ? 1 : 2);
}

// ---------------- LayerNorm (one warp per token), optional window-gather ----------------
template<int GATHER>
__global__ void ln_kernel(const float* __restrict__ src, const float* __restrict__ g,
                          const float* __restrict__ bta, float* __restrict__ dst) {
    int tok  = blockIdx.x * 8 + (threadIdx.x >> 5);
    int lane = threadIdx.x & 31;
    if (tok >= TTOK) return;
    int srow = GATHER ? win_src_token(tok) : tok;
    const float* p = src + (size_t)srow * DIM;
    float v[6];
    float s = 0.f;
#pragma unroll
    for (int j = 0; j < 6; j++) { v[j] = p[j*32 + lane]; s += v[j]; }
#pragma unroll
    for (int o = 16; o; o >>= 1) s += __shfl_xor_sync(0xffffffffu, s, o);
    float mu = s * (1.f / DIM);
    float vr = 0.f;
#pragma unroll
    for (int j = 0; j < 6; j++) { float d = v[j] - mu; vr += d * d; }
#pragma unroll
    for (int o = 16; o; o >>= 1) vr += __shfl_xor_sync(0xffffffffu, vr, o);
    float r = rsqrtf(vr * (1.f / DIM) + 1e-5f);
    float* q = dst + (size_t)tok * DIM;
#pragma unroll
    for (int j = 0; j < 6; j++) {
        int c = j*32 + lane;
        q[c] = (v[j] - mu) * r * g[c] + bta[c];
    }
}

// ---------------- tiled SGEMM with fused epilogues ----------------
// C[M,Nc] = A[M,K] @ W[K,Nc]; M%128==0, Nc%64==0, K%16==0 (all hold here)
// EPI 0: qkv split (+bias, q*SCALE) -> out/out2/out3 as [win][head][n][32]
// EPI 1: proj +bias, scatter to token order, add residual extra_in -> out
// EPI 2: fc1 +bias, exact gelu -> out
// EPI 3: fc2 +bias + extra_in -> out
template<int EPI>
__global__ __launch_bounds__(256)
void gemm_kernel(const float* __restrict__ A, const float* __restrict__ W,
                 const float* __restrict__ bias, int M, int K, int Nc,
                 const float* __restrict__ extra_in,
                 float* __restrict__ out, float* __restrict__ out2, float* __restrict__ out3) {
    __shared__ float As[16][128];
    __shared__ float Bs[16][64];

    int t  = threadIdx.x;
    int tx = t & 15;          // col group (4 cols)
    int ty = t >> 4;          // row group (8 rows)
    int br = blockIdx.y * 128;
    int bc = blockIdx.x * 64;

    // A-load mapping: each thread loads 8 consecutive K of one row
    int arow = t >> 1;
    int akq  = (t & 1) * 8;
    // B-load mapping: one float4
    int bkr = t >> 4;
    int bcq = (t & 15) * 4;

    float acc[8][4];
#pragma unroll
    for (int i = 0; i < 8; i++)
#pragma unroll
        for (int j = 0; j < 4; j++) acc[i][j] = 0.f;

    for (int k0 = 0; k0 < K; k0 += 16) {
        const float* ap = A + (size_t)(br + arow) * K + k0 + akq;
        float4 f1 = *(const float4*)ap;
        float4 f2 = *(const float4*)(ap + 4);
        As[akq+0][arow] = f1.x; As[akq+1][arow] = f1.y;
        As[akq+2][arow] = f1.z; As[akq+3][arow] = f1.w;
        As[akq+4][arow] = f2.x; As[akq+5][arow] = f2.y;
        As[akq+6][arow] = f2.z; As[akq+7][arow] = f2.w;
        float4 fb = *(const float4*)(W + (size_t)(k0 + bkr) * Nc + bc + bcq);
        *(float4*)&Bs[bkr][bcq] = fb;
        __syncthreads();
#pragma unroll
        for (int k = 0; k < 16; k++) {
            float a[8], b[4];
#pragma unroll
            for (int i = 0; i < 8; i++) a[i] = As[k][ty*8 + i];
#pragma unroll
            for (int j = 0; j < 4; j++) b[j] = Bs[k][tx*4 + j];
#pragma unroll
            for (int i = 0; i < 8; i++)
#pragma unroll
                for (int j = 0; j < 4; j++) acc[i][j] = fmaf(a[i], b[j], acc[i][j]);
        }
        __syncthreads();
    }

#pragma unroll
    for (int i = 0; i < 8; i++) {
        int row = br + ty*8 + i;
#pragma unroll
        for (int j = 0; j < 4; j++) {
            int col = bc + tx*4 + j;
            float val = acc[i][j] + bias[col];
            if (EPI == 0) {
                int s  = col / DIM;
                int hh = (col % DIM) >> 5;
                int d  = col & 31;
                int win = row / NTOK, n = row - win * NTOK;
                size_t off = (((size_t)(win*HEADS + hh)) * NTOK + n) * HD + d;
                if (s == 0)      out [off] = val * SCALE;
                else if (s == 1) out2[off] = val;
                else             out3[off] = val;
            } else if (EPI == 1) {
                int dst = win_src_token(row);
                size_t off = (size_t)dst * DIM + col;
                out[off] = extra_in[off] + val;
            } else if (EPI == 2) {
                out[(size_t)row * (4*DIM) + col] = 0.5f * val * (1.f + erff(val * 0.70710678118654752f));
            } else {
                size_t off = (size_t)row * DIM + col;
                out[off] = val + extra_in[off];
            }
        }
    }
}

// ---------------- attention: one block per (window, head) ----------------
__global__ __launch_bounds__(128)
void attn_kernel(const float* __restrict__ bias_table) {
    int bh   = blockIdx.x;               // win*HEADS + head
    int win  = bh / HEADS;
    int head = bh - win * HEADS;

    __shared__ float qs[NTOK*33];
    __shared__ float ks[NTOK*33];
    __shared__ float vs[NTOK*33];
    __shared__ float sc[NTOK][52];

    const float* qp = g_q + (size_t)bh * (NTOK*HD);
    const float* kp = g_k + (size_t)bh * (NTOK*HD);
    const float* vp = g_v + (size_t)bh * (NTOK*HD);

    int t = threadIdx.x;
    for (int i = t; i < NTOK*HD; i += 128) {
        int n = i >> 5, d = i & 31;
        qs[n*33 + d] = qp[i];
        ks[n*33 + d] = kp[i];
        vs[n*33 + d] = vp[i];
    }
    __syncthreads();

    int wi = win & 63;
    int wy = wi >> 3, wx = wi & 7;

    // scores + bias + shift mask
    for (int idx = t; idx < NTOK*NTOK; idx += 128) {
        int i = idx / NTOK, j = idx - i * NTOK;
        float s = 0.f;
#pragma unroll
        for (int k2 = 0; k2 < HD; k2++) s = fmaf(qs[i*33 + k2], ks[j*33 + k2], s);
        int yi = i / WS, xi = i - yi*WS;
        int yj = j / WS, xj = j - yj*WS;
        int rel = (yi - yj + WS - 1) * (2*WS - 1) + (xi - xj + WS - 1);
        s += bias_table[rel * HEADS + head];
        int li = region(wy*WS + yi) * 3 + region(wx*WS + xi);
        int lj = region(wy*WS + yj) * 3 + region(wx*WS + xj);
        if (li != lj) s -= 100.f;
        sc[i][j] = s;
    }
    __syncthreads();

    // softmax over rows (one warp handles rows warp, warp+4, ...)
    int warp = t >> 5, lane = t & 31;
    for (int row = warp; row < NTOK; row += 4) {
        float a = (lane      < NTOK) ? sc[row][lane]      : -1e30f;
        float b = (lane + 32 < NTOK) ? sc[row][lane + 32] : -1e30f;
        float mx = fmaxf(a, b);
#pragma unroll
        for (int o = 16; o; o >>= 1) mx = fmaxf(mx, __shfl_xor_sync(0xffffffffu, mx, o));
        float ea = (lane      < NTOK) ? __expf(a - mx) : 0.f;
        float eb = (lane + 32 < NTOK) ? __expf(b - mx) : 0.f;
        float sum = ea + eb;
#pragma unroll
        for (int o = 16; o; o >>= 1) sum += __shfl_xor_sync(0xffffffffu, sum, o);
        float inv = 1.f / sum;
        if (lane      < NTOK) sc[row][lane]      = ea * inv;
        if (lane + 32 < NTOK) sc[row][lane + 32] = eb * inv;
    }
    __syncthreads();

    // out = attn @ v  ->  g_ao[(win*49+i)*192 + head*32 + d]
    float* op = g_ao + ((size_t)win * NTOK) * DIM + head * HD;
    for (int idx = t; idx < NTOK*HD; idx += 128) {
        int i = idx >> 5, d = idx & 31;
        float s = 0.f;
#pragma unroll
        for (int j = 0; j < NTOK; j++) s = fmaf(sc[i][j], vs[j*33 + d], s);
        op[(size_t)i * DIM + d] = s;
    }
}

// ---------------- launch ----------------
static float* sym_ptr(const void* sym) {
    void* p = nullptr;
    cudaGetSymbolAddress(&p, sym);
    return (float*)p;
}

extern "C" void kernel_launch(void* const* d_in, const int* in_sizes, int n_in,
                              void* d_out, int out_size) {
    const float* x       = (const float*)d_in[0];
    const float* n1g     = (const float*)d_in[1];
    const float* n1b     = (const float*)d_in[2];
    const float* qkv_w   = (const float*)d_in[3];
    const float* qkv_b   = (const float*)d_in[4];
    const float* proj_w  = (const float*)d_in[5];
    const float* proj_b  = (const float*)d_in[6];
    const float* btab    = (const float*)d_in[7];
    const float* n2g     = (const float*)d_in[8];
    const float* n2b     = (const float*)d_in[9];
    const float* fc1_w   = (const float*)d_in[10];
    const float* fc1_b   = (const float*)d_in[11];
    const float* fc2_w   = (const float*)d_in[12];
    const float* fc2_b   = (const float*)d_in[13];
    float* outp = (float*)d_out;

    float* hln = sym_ptr(g_hln);
    float* q   = sym_ptr(g_q);
    float* k   = sym_ptr(g_k);
    float* v   = sym_ptr(g_v);
    float* ao  = sym_ptr(g_ao);
    float* xn  = sym_ptr(g_xn);
    float* ml  = sym_ptr(g_ml);

    // 1. LN1 + roll + window partition
    ln_kernel<1><<<TTOK/8, 256>>>(x, n1g, n1b, hln);
    // 2. qkv GEMM (+ bias, q pre-scaled, split into q/k/v head layout)
    gemm_kernel<0><<<dim3((3*DIM)/64, TTOK/128), 256>>>(hln, qkv_w, qkv_b, TTOK, DIM, 3*DIM,
                                                        nullptr, q, k, v);
    // 3. windowed attention (bias + mask inline)
    attn_kernel<<<BW*HEADS, 128>>>(btab);
    // 4. proj GEMM + reverse window/roll scatter + residual
    gemm_kernel<1><<<dim3(DIM/64, TTOK/128), 256>>>(ao, proj_w, proj_b, TTOK, DIM, DIM,
                                                    x, xn, nullptr, nullptr);
    // 5. LN2 (reuse hln buffer)
    ln_kernel<0><<<TTOK/8, 256>>>(xn, n2g, n2b, hln);
    // 6. fc1 GEMM + exact gelu
    gemm_kernel<2><<<dim3((4*DIM)/64, TTOK/128), 256>>>(hln, fc1_w, fc1_b, TTOK, DIM, 4*DIM,
                                                        nullptr, ml, nullptr, nullptr);
    // 7. fc2 GEMM + residual -> output
    gemm_kernel<3><<<dim3(DIM/64, TTOK/128), 256>>>(ml, fc2_w, fc2_b, TTOK, 4*DIM, DIM,
                                                    xn, outp, nullptr, nullptr);
}

// round 3
// speedup vs baseline: 1.5733x; 1.5733x over previous
#include <cuda_runtime.h>
#include <math.h>

// ---------------- constants ----------------
#define RES   56
#define WS    7
#define SHIFT 3
#define DIM   192
#define HEADS 6
#define HD    32
#define NTOK  49
#define BATCH 32
#define NWIN  64
#define BW    (BATCH*NWIN)        // 2048 windows
#define TTOK  (BW*NTOK)           // 100352 rows
#define SCALE 0.17677669529663687f

// ---------------- scratch ----------------
__device__ float g_hln[TTOK*DIM];
__device__ float g_q  [TTOK*DIM];
__device__ float g_k  [TTOK*DIM];
__device__ float g_v  [TTOK*DIM];
__device__ float g_ao [TTOK*DIM];
__device__ float g_xn [TTOK*DIM];
__device__ float g_ml [TTOK*4*DIM];

__device__ __forceinline__ int win_src_token(int m) {
    int win = m / NTOK, n = m - win * NTOK;
    int b   = win >> 6, wi = win & 63;
    int wy  = wi >> 3,  wx = wi & 7;
    int py  = n / WS,   px = n - py * WS;
    int y = wy * WS + py + SHIFT; if (y >= RES) y -= RES;
    int x = wx * WS + px + SHIFT; if (x >= RES) x -= RES;
    return b * (RES*RES) + y * RES + x;
}

__device__ __forceinline__ int region(int c) {
    return (c < RES - WS) ? 0 : ((c < RES - SHIFT) ? 1 : 2);
}

// ---------------- LayerNorm ----------------
template<int GATHER>
__global__ void ln_kernel(const float* __restrict__ src, const float* __restrict__ g,
                          const float* __restrict__ bta, float* __restrict__ dst) {
    int tok  = blockIdx.x * 8 + (threadIdx.x >> 5);
    int lane = threadIdx.x & 31;
    if (tok >= TTOK) return;
    int srow = GATHER ? win_src_token(tok) : tok;
    const float* p = src + (size_t)srow * DIM;
    float v[6];
    float s = 0.f;
#pragma unroll
    for (int j = 0; j < 6; j++) { v[j] = p[j*32 + lane]; s += v[j]; }
#pragma unroll
    for (int o = 16; o; o >>= 1) s += __shfl_xor_sync(0xffffffffu, s, o);
    float mu = s * (1.f / DIM);
    float vr = 0.f;
#pragma unroll
    for (int j = 0; j < 6; j++) { float d = v[j] - mu; vr += d * d; }
#pragma unroll
    for (int o = 16; o; o >>= 1) vr += __shfl_xor_sync(0xffffffffu, vr, o);
    float r = rsqrtf(vr * (1.f / DIM) + 1e-5f);
    float* q = dst + (size_t)tok * DIM;
#pragma unroll
    for (int j = 0; j < 6; j++) {
        int c = j*32 + lane;
        q[c] = (v[j] - mu) * r * g[c] + bta[c];
    }
}

// ---------------- TF32 tensor-core GEMM with fused epilogues ----------------
__device__ __forceinline__ unsigned f2tf(float x) {
    unsigned r; asm("cvt.rna.tf32.f32 %0, %1;" : "=r"(r) : "f"(x)); return r;
}

__device__ __forceinline__ void mma8(float* c, const unsigned* a, const unsigned* b) {
    asm volatile("mma.sync.aligned.m16n8k8.row.col.f32.tf32.tf32.f32 "
        "{%0,%1,%2,%3},{%4,%5,%6,%7},{%8,%9},{%0,%1,%2,%3};"
        : "+f"(c[0]), "+f"(c[1]), "+f"(c[2]), "+f"(c[3])
        : "r"(a[0]), "r"(a[1]), "r"(a[2]), "r"(a[3]), "r"(b[0]), "r"(b[1]));
}

// C[M,Nc] = A[M,K] @ W[K,Nc]; block tile 128x64, 8 warps (4m x 2n), warp tile 32x32.
// EPI 0: qkv split (+bias, q*SCALE); EPI 1: proj+scatter+residual;
// EPI 2: fc1+gelu; EPI 3: fc2+residual.
template<int EPI>
__global__ __launch_bounds__(256)
void gemm_tc(const float* __restrict__ A, const float* __restrict__ W,
             const float* __restrict__ bias, int K, int Nc,
             const float* __restrict__ extra_in,
             float* __restrict__ out, float* __restrict__ out2, float* __restrict__ out3) {
    __shared__ unsigned As[16][136];   // stride 136 ≡ 8 mod 32 -> conflict-free frag loads
    __shared__ unsigned Bs[16][72];    // 64 cols + 8 pad; stride 72 ≡ 8 mod 32

    int t    = threadIdx.x;
    int br   = blockIdx.y * 128;
    int bc   = blockIdx.x * 64;
    int lane = t & 31, warp = t >> 5;
    int wm   = warp & 3, wn = warp >> 2;
    int gid  = lane >> 2, tig = lane & 3;

    // staging mapping
    int arow = t >> 1, akq = (t & 1) * 8;     // A: each thread 8 consecutive K of one row
    int bkr  = t >> 4, bcq = (t & 15) * 4;    // B: one float4

    float acc[2][4][4];
#pragma unroll
    for (int mt = 0; mt < 2; mt++)
#pragma unroll
        for (int nt = 0; nt < 4; nt++)
#pragma unroll
            for (int e = 0; e < 4; e++) acc[mt][nt][e] = 0.f;

    // prefetch tile 0
    const float* ap0 = A + (size_t)(br + arow) * K + akq;
    float4 pa0 = *(const float4*)ap0;
    float4 pa1 = *(const float4*)(ap0 + 4);
    float4 pb  = *(const float4*)(W + (size_t)bkr * Nc + bc + bcq);

    int k0 = 0;
    for (;;) {
        // stage regs -> smem (convert to tf32)
        As[akq+0][arow] = f2tf(pa0.x); As[akq+1][arow] = f2tf(pa0.y);
        As[akq+2][arow] = f2tf(pa0.z); As[akq+3][arow] = f2tf(pa0.w);
        As[akq+4][arow] = f2tf(pa1.x); As[akq+5][arow] = f2tf(pa1.y);
        As[akq+6][arow] = f2tf(pa1.z); As[akq+7][arow] = f2tf(pa1.w);
        uint4 ub = make_uint4(f2tf(pb.x), f2tf(pb.y), f2tf(pb.z), f2tf(pb.w));
        *(uint4*)&Bs[bkr][bcq] = ub;
        __syncthreads();

        k0 += 16;
        if (k0 < K) {   // prefetch next tile while computing
            const float* ap = A + (size_t)(br + arow) * K + k0 + akq;
            pa0 = *(const float4*)ap;
            pa1 = *(const float4*)(ap + 4);
            pb  = *(const float4*)(W + (size_t)(k0 + bkr) * Nc + bc + bcq);
        }

#pragma unroll
        for (int kk = 0; kk < 16; kk += 8) {
            unsigned a[2][4], b[4][2];
            int k1 = kk + tig, k2 = kk + tig + 4;
#pragma unroll
            for (int mt = 0; mt < 2; mt++) {
                int rb = wm*32 + mt*16 + gid;
                a[mt][0] = As[k1][rb];   a[mt][1] = As[k1][rb + 8];
                a[mt][2] = As[k2][rb];   a[mt][3] = As[k2][rb + 8];
            }
#pragma unroll
            for (int nt = 0; nt < 4; nt++) {
                int cb = wn*32 + nt*8 + gid;
                b[nt][0] = Bs[k1][cb];   b[nt][1] = Bs[k2][cb];
            }
#pragma unroll
            for (int mt = 0; mt < 2; mt++)
#pragma unroll
                for (int nt = 0; nt < 4; nt++) mma8(acc[mt][nt], a[mt], b[nt]);
        }

        if (k0 >= K) break;
        __syncthreads();
    }

    // epilogue
#pragma unroll
    for (int mt = 0; mt < 2; mt++) {
#pragma unroll
        for (int nt = 0; nt < 4; nt++) {
#pragma unroll
            for (int e = 0; e < 4; e++) {
                int row = br + wm*32 + mt*16 + gid + ((e >= 2) ? 8 : 0);
                int col = bc + wn*32 + nt*8 + tig*2 + (e & 1);
                float val = acc[mt][nt][e] + bias[col];
                if (EPI == 0) {
                    int s   = col / DIM;
                    int hh  = (col % DIM) >> 5;
                    int d   = col & 31;
                    int win = row / NTOK, n = row - win * NTOK;
                    size_t off = (((size_t)(win*HEADS + hh)) * NTOK + n) * HD + d;
                    if (s == 0)      out [off] = val * SCALE;
                    else if (s == 1) out2[off] = val;
                    else             out3[off] = val;
                } else if (EPI == 1) {
                    int dst = win_src_token(row);
                    size_t off = (size_t)dst * DIM + col;
                    out[off] = extra_in[off] + val;
                } else if (EPI == 2) {
                    out[(size_t)row * (4*DIM) + col] =
                        0.5f * val * (1.f + erff(val * 0.70710678118654752f));
                } else {
                    size_t off = (size_t)row * DIM + col;
                    out[off] = val + extra_in[off];
                }
            }
        }
    }
}

// ---------------- attention: one block per (window, head) ----------------
__global__ __launch_bounds__(128)
void attn_kernel(const float* __restrict__ bias_table) {
    int bh   = blockIdx.x;
    int win  = bh / HEADS;
    int head = bh - win * HEADS;

    __shared__ float qs[NTOK*33];
    __shared__ float ks[NTOK*33];
    __shared__ float vs[NTOK*33];
    __shared__ float sc[NTOK][52];

    const float* qp = g_q + (size_t)bh * (NTOK*HD);
    const float* kp = g_k + (size_t)bh * (NTOK*HD);
    const float* vp = g_v + (size_t)bh * (NTOK*HD);

    int t = threadIdx.x;
    for (int i = t; i < NTOK*HD; i += 128) {
        int n = i >> 5, d = i & 31;
        qs[n*33 + d] = qp[i];
        ks[n*33 + d] = kp[i];
        vs[n*33 + d] = vp[i];
    }
    __syncthreads();

    int wi = win & 63;
    int wy = wi >> 3, wx = wi & 7;

    for (int idx = t; idx < NTOK*NTOK; idx += 128) {
        int i = idx / NTOK, j = idx - i * NTOK;
        float s = 0.f;
#pragma unroll
        for (int k2 = 0; k2 < HD; k2++) s = fmaf(qs[i*33 + k2], ks[j*33 + k2], s);
        int yi = i / WS, xi = i - yi*WS;
        int yj = j / WS, xj = j - yj*WS;
        int rel = (yi - yj + WS - 1) * (2*WS - 1) + (xi - xj + WS - 1);
        s += bias_table[rel * HEADS + head];
        int li = region(wy*WS + yi) * 3 + region(wx*WS + xi);
        int lj = region(wy*WS + yj) * 3 + region(wx*WS + xj);
        if (li != lj) s -= 100.f;
        sc[i][j] = s;
    }
    __syncthreads();

    int warp = t >> 5, lane = t & 31;
    for (int row = warp; row < NTOK; row += 4) {
        float a = (lane      < NTOK) ? sc[row][lane]      : -1e30f;
        float b = (lane + 32 < NTOK) ? sc[row][lane + 32] : -1e30f;
        float mx = fmaxf(a, b);
#pragma unroll
        for (int o = 16; o; o >>= 1) mx = fmaxf(mx, __shfl_xor_sync(0xffffffffu, mx, o));
        float ea = (lane      < NTOK) ? __expf(a - mx) : 0.f;
        float eb = (lane + 32 < NTOK) ? __expf(b - mx) : 0.f;
        float sum = ea + eb;
#pragma unroll
        for (int o = 16; o; o >>= 1) sum += __shfl_xor_sync(0xffffffffu, sum, o);
        float inv = 1.f / sum;
        if (lane      < NTOK) sc[row][lane]      = ea * inv;
        if (lane + 32 < NTOK) sc[row][lane + 32] = eb * inv;
    }
    __syncthreads();

    float* op = g_ao + ((size_t)win * NTOK) * DIM + head * HD;
    for (int idx = t; idx < NTOK*HD; idx += 128) {
        int i = idx >> 5, d = idx & 31;
        float s = 0.f;
#pragma unroll
        for (int j = 0; j < NTOK; j++) s = fmaf(sc[i][j], vs[j*33 + d], s);
        op[(size_t)i * DIM + d] = s;
    }
}

// ---------------- launch ----------------
static float* sym_ptr(const void* sym) {
    void* p = nullptr;
    cudaGetSymbolAddress(&p, sym);
    return (float*)p;
}

extern "C" void kernel_launch(void* const* d_in, const int* in_sizes, int n_in,
                              void* d_out, int out_size) {
    const float* x       = (const float*)d_in[0];
    const float* n1g     = (const float*)d_in[1];
    const float* n1b     = (const float*)d_in[2];
    const float* qkv_w   = (const float*)d_in[3];
    const float* qkv_b   = (const float*)d_in[4];
    const float* proj_w  = (const float*)d_in[5];
    const float* proj_b  = (const float*)d_in[6];
    const float* btab    = (const float*)d_in[7];
    const float* n2g     = (const float*)d_in[8];
    const float* n2b     = (const float*)d_in[9];
    const float* fc1_w   = (const float*)d_in[10];
    const float* fc1_b   = (const float*)d_in[11];
    const float* fc2_w   = (const float*)d_in[12];
    const float* fc2_b   = (const float*)d_in[13];
    float* outp = (float*)d_out;

    float* hln = sym_ptr(g_hln);
    float* q   = sym_ptr(g_q);
    float* k   = sym_ptr(g_k);
    float* v   = sym_ptr(g_v);
    float* ao  = sym_ptr(g_ao);
    float* xn  = sym_ptr(g_xn);
    float* ml  = sym_ptr(g_ml);

    // 1. LN1 + roll + window partition
    ln_kernel<1><<<TTOK/8, 256>>>(x, n1g, n1b, hln);
    // 2. qkv GEMM (tensor cores)
    gemm_tc<0><<<dim3((3*DIM)/64, TTOK/128), 256>>>(hln, qkv_w, qkv_b, DIM, 3*DIM,
                                                    nullptr, q, k, v);
    // 3. windowed attention
    attn_kernel<<<BW*HEADS, 128>>>(btab);
    // 4. proj GEMM + reverse scatter + residual
    gemm_tc<1><<<dim3(DIM/64, TTOK/128), 256>>>(ao, proj_w, proj_b, DIM, DIM,
                                                x, xn, nullptr, nullptr);
    // 5. LN2
    ln_kernel<0><<<TTOK/8, 256>>>(xn, n2g, n2b, hln);
    // 6. fc1 GEMM + gelu
    gemm_tc<2><<<dim3((4*DIM)/64, TTOK/128), 256>>>(hln, fc1_w, fc1_b, DIM, 4*DIM,
                                                    nullptr, ml, nullptr, nullptr);
    // 7. fc2 GEMM + residual -> output
    gemm_tc<3><<<dim3(DIM/64, TTOK/128), 256>>>(ml, fc2_w, fc2_b, 4*DIM, DIM,
                                                xn, outp, nullptr, nullptr);
}